// round 2
// baseline (speedup 1.0000x reference)
#include <cuda_runtime.h>
#include <math.h>

#define BB 64
#define TT 512
#define DIN 862
#define HH 1024
#define GG 4096

#define NCTA 128
#define CHUNK 128
#define NCHUNK (HH / CHUNK)   // 8

// Scratch (allocation-free rule: __device__ globals)
static __device__ float g_xg[(size_t)TT * BB * GG];   // [T*B][G] gate preactivations
static __device__ float g_h1[(size_t)TT * BB * HH];   // layer-0 output, rows m = t*B+b
static __device__ float g_hT[2][HH * BB];             // transposed h state [j][b], ping-pong
static __device__ unsigned g_gen;
static __device__ unsigned g_cnt;

__global__ void zero_state_kernel() {
    int i = blockIdx.x * blockDim.x + threadIdx.x;
    if (i == 0) { g_gen = 0u; g_cnt = 0u; }
    const int n = 2 * HH * BB;
    for (; i < n; i += gridDim.x * blockDim.x) ((float*)g_hT)[i] = 0.f;
}

// C[m][n] = sum_k A[row(m)][k] * W[n][k] + b1[n] + b2[n] -> g_xg[m*G + n]
// PERM=1: A row = b*T + t (x is [B][T][D], m = t*B+b); PERM=0: A row = m (h1 layout).
template<int PERM>
__global__ void __launch_bounds__(256, 2)
sgemm_input(const float* __restrict__ Aext, int use_h1, int lda, int K,
            const float* __restrict__ W,
            const float* __restrict__ b1, const float* __restrict__ b2)
{
    const float* A = use_h1 ? (const float*)g_h1 : Aext;
    __shared__ float As[16][132];
    __shared__ float Bs[16][132];
    const int n0 = blockIdx.x * 128;
    const int m0 = blockIdx.y * 128;
    const int tid = threadIdx.x;
    const int tx = tid & 15, ty = tid >> 4;

    float bias[8];
#pragma unroll
    for (int j = 0; j < 8; j++) {
        int n = n0 + tx * 8 + j;
        bias[j] = b1[n] + b2[n];
    }

    float acc[8][8];
#pragma unroll
    for (int i = 0; i < 8; i++)
#pragma unroll
        for (int j = 0; j < 8; j++) acc[i][j] = 0.f;

    for (int k0 = 0; k0 < K; k0 += 16) {
#pragma unroll
        for (int i = 0; i < 4; i++) {
            int idx = tid + i * 256;
            int r = idx >> 3, k2 = idx & 7;
            int k = k0 + k2 * 2;
            int mm = m0 + r;
            long ar = PERM ? ((long)(mm & 63) * TT + (mm >> 6)) : (long)mm;
            float2 v = make_float2(0.f, 0.f);
            if (k < K) v = *(const float2*)(A + ar * (long)lda + k);
            As[k2 * 2][r] = v.x; As[k2 * 2 + 1][r] = v.y;
        }
#pragma unroll
        for (int i = 0; i < 4; i++) {
            int idx = tid + i * 256;
            int r = idx >> 3, k2 = idx & 7;
            int k = k0 + k2 * 2;
            float2 v = make_float2(0.f, 0.f);
            if (k < K) v = *(const float2*)(W + (long)(n0 + r) * lda + k);
            Bs[k2 * 2][r] = v.x; Bs[k2 * 2 + 1][r] = v.y;
        }
        __syncthreads();
#pragma unroll
        for (int k = 0; k < 16; k++) {
            float a[8], bv[8];
            *(float4*)&a[0]  = *(const float4*)&As[k][ty * 8];
            *(float4*)&a[4]  = *(const float4*)&As[k][ty * 8 + 4];
            *(float4*)&bv[0] = *(const float4*)&Bs[k][tx * 8];
            *(float4*)&bv[4] = *(const float4*)&Bs[k][tx * 8 + 4];
#pragma unroll
            for (int i = 0; i < 8; i++)
#pragma unroll
                for (int j = 0; j < 8; j++)
                    acc[i][j] = fmaf(a[i], bv[j], acc[i][j]);
        }
        __syncthreads();
    }
#pragma unroll
    for (int i = 0; i < 8; i++) {
        int mm = m0 + ty * 8 + i;
        float* op = &g_xg[(size_t)mm * GG + n0 + tx * 8];
#pragma unroll
        for (int j = 0; j < 8; j++) op[j] = acc[i][j] + bias[j];
    }
}

// Persistent recurrence. 128 CTAs x 256 threads, 1 CTA/SM (smem-bound).
// CTA owns j-tile of 8 (all 4 gates = 32 W rows, cached in smem for all 512 steps).
// h state transposed [j][b] in global, staged per-128-k chunk (double buffered).
// c lives in smem for the whole sequence. Hand-rolled grid barrier per step.
// smem: ws 32x1028 | hs 2x(128x64) | ab 32x64 | cs 8x64  = 207,360 B
#define SMEM_FLOATS (32 * 1028 + 2 * CHUNK * 64 + 32 * 64 + 8 * 64)

template<int LAYER>
__global__ void __launch_bounds__(256, 1)
lstm_persistent(const float* __restrict__ W_hh, float* __restrict__ out_ext)
{
    extern __shared__ float sm[];
    float* ws = sm;                       // [32][1028]
    float* hs = ws + 32 * 1028;           // 2 x [128][64]
    float* ab = hs + 2 * CHUNK * 64;      // [32][64] gate preact staging
    float* cs = ab + 32 * 64;             // [8*64] cell state

    const int tid = threadIdx.x;
    const int j0 = blockIdx.x * 8;

    // Load W tile: row rr -> (jj = rr>>2, g = rr&3), global row g*1024 + j0 + jj
#pragma unroll 4
    for (int i = 0; i < 32; i++) {
        int grow = ((i & 3) << 10) + j0 + (i >> 2);
        float4 v = *(const float4*)(W_hh + (size_t)grow * HH + tid * 4);
        *(float4*)&ws[i * 1028 + tid * 4] = v;
    }
    for (int i = tid; i < 512; i += 256) cs[i] = 0.f;
    __syncthreads();

    const int w  = tid >> 5;
    const int lr = (tid >> 3) & 3;
    const int lc = tid & 7;
    const int rr0 = (w >> 1) * 8 + lr * 2;     // row pair rr0, rr0+1
    const int b0  = (w & 1) * 32 + lc * 4;     // 4 batches
    const float* w0p = ws + rr0 * 1028;
    const float* w1p = w0p + 1028;

    unsigned gen = 0;

    for (int t = 0; t < TT; t++) {
        const float* hin = g_hT[t & 1];
        float*       hout = g_hT[(t + 1) & 1];

        // stage chunk 0
        {
            const float4* src = (const float4*)hin;
            float4* dst = (float4*)hs;
#pragma unroll
            for (int i = 0; i < 8; i++) dst[tid + i * 256] = src[tid + i * 256];
        }
        __syncthreads();

        float4 acc0 = make_float4(0.f, 0.f, 0.f, 0.f);
        float4 acc1 = make_float4(0.f, 0.f, 0.f, 0.f);

        for (int c = 0; c < NCHUNK; c++) {
            const int cb = c & 1;
            if (c < NCHUNK - 1) {
                const float4* src = (const float4*)(hin + (c + 1) * CHUNK * 64);
                float4* dst = (float4*)(hs + (cb ^ 1) * (CHUNK * 64));
#pragma unroll
                for (int i = 0; i < 8; i++) dst[tid + i * 256] = src[tid + i * 256];
            }
            const float* hc = hs + cb * (CHUNK * 64);
            const int kbase = c * CHUNK;
#pragma unroll 8
            for (int kk = 0; kk < CHUNK; kk += 4) {
                float4 w0 = *(const float4*)(w0p + kbase + kk);
                float4 w1 = *(const float4*)(w1p + kbase + kk);
                float4 h0 = *(const float4*)(hc + (kk + 0) * 64 + b0);
                float4 h1 = *(const float4*)(hc + (kk + 1) * 64 + b0);
                float4 h2 = *(const float4*)(hc + (kk + 2) * 64 + b0);
                float4 h3 = *(const float4*)(hc + (kk + 3) * 64 + b0);
                acc0.x = fmaf(w0.x, h0.x, acc0.x); acc0.y = fmaf(w0.x, h0.y, acc0.y);
                acc0.z = fmaf(w0.x, h0.z, acc0.z); acc0.w = fmaf(w0.x, h0.w, acc0.w);
                acc0.x = fmaf(w0.y, h1.x, acc0.x); acc0.y = fmaf(w0.y, h1.y, acc0.y);
                acc0.z = fmaf(w0.y, h1.z, acc0.z); acc0.w = fmaf(w0.y, h1.w, acc0.w);
                acc0.x = fmaf(w0.z, h2.x, acc0.x); acc0.y = fmaf(w0.z, h2.y, acc0.y);
                acc0.z = fmaf(w0.z, h2.z, acc0.z); acc0.w = fmaf(w0.z, h2.w, acc0.w);
                acc0.x = fmaf(w0.w, h3.x, acc0.x); acc0.y = fmaf(w0.w, h3.y, acc0.y);
                acc0.z = fmaf(w0.w, h3.z, acc0.z); acc0.w = fmaf(w0.w, h3.w, acc0.w);
                acc1.x = fmaf(w1.x, h0.x, acc1.x); acc1.y = fmaf(w1.x, h0.y, acc1.y);
                acc1.z = fmaf(w1.x, h0.z, acc1.z); acc1.w = fmaf(w1.x, h0.w, acc1.w);
                acc1.x = fmaf(w1.y, h1.x, acc1.x); acc1.y = fmaf(w1.y, h1.y, acc1.y);
                acc1.z = fmaf(w1.y, h1.z, acc1.z); acc1.w = fmaf(w1.y, h1.w, acc1.w);
                acc1.x = fmaf(w1.z, h2.x, acc1.x); acc1.y = fmaf(w1.z, h2.y, acc1.y);
                acc1.z = fmaf(w1.z, h2.z, acc1.z); acc1.w = fmaf(w1.z, h2.w, acc1.w);
                acc1.x = fmaf(w1.w, h3.x, acc1.x); acc1.y = fmaf(w1.w, h3.y, acc1.y);
                acc1.z = fmaf(w1.w, h3.z, acc1.z); acc1.w = fmaf(w1.w, h3.w, acc1.w);
            }
            __syncthreads();
        }

        *(float4*)&ab[rr0 * 64 + b0] = acc0;
        *(float4*)&ab[(rr0 + 1) * 64 + b0] = acc1;
        __syncthreads();

        // Pointwise LSTM update: 512 cells/CTA, 2 per thread
#pragma unroll
        for (int u = 0; u < 2; u++) {
            int cell = tid + u * 256;
            int jj = cell >> 6, b = cell & 63;
            size_t xbase = ((size_t)t * BB + b) * GG + j0 + jj;
            float pi = ab[(jj * 4 + 0) * 64 + b] + g_xg[xbase];
            float pf = ab[(jj * 4 + 1) * 64 + b] + g_xg[xbase + 1024];
            float pg = ab[(jj * 4 + 2) * 64 + b] + g_xg[xbase + 2048];
            float po = ab[(jj * 4 + 3) * 64 + b] + g_xg[xbase + 3072];
            float ig = 1.f / (1.f + expf(-pi));
            float fg = 1.f / (1.f + expf(-pf));
            float gc = tanhf(pg);
            float og = 1.f / (1.f + expf(-po));
            float cn = fg * cs[cell] + ig * gc;
            float hn = og * tanhf(cn);
            cs[cell] = cn;
            hout[(j0 + jj) * 64 + b] = hn;
            if (LAYER == 0) g_h1[((size_t)t * BB + b) * HH + j0 + jj] = hn;
            else            out_ext[((size_t)b * TT + t) * HH + j0 + jj] = hn;
        }

        // Grid barrier: release h writes, wait for all CTAs
        __threadfence();
        __syncthreads();
        gen++;
        if (tid == 0) {
            if (atomicAdd(&g_cnt, 1u) == NCTA - 1) {
                g_cnt = 0u;
                __threadfence();
                *(volatile unsigned*)&g_gen = gen;
            } else {
                while (*(volatile unsigned*)&g_gen < gen) { }
                __threadfence();
            }
        }
        __syncthreads();
    }
}

extern "C" void kernel_launch(void* const* d_in, const int* in_sizes, int n_in,
                              void* d_out, int out_size)
{
    (void)in_sizes; (void)n_in; (void)out_size;
    const float* x     = (const float*)d_in[0];
    const float* W_ih0 = (const float*)d_in[1];
    const float* W_hh0 = (const float*)d_in[2];
    const float* b_ih0 = (const float*)d_in[3];
    const float* b_hh0 = (const float*)d_in[4];
    const float* W_ih1 = (const float*)d_in[5];
    const float* W_hh1 = (const float*)d_in[6];
    const float* b_ih1 = (const float*)d_in[7];
    const float* b_hh1 = (const float*)d_in[8];
    float* out = (float*)d_out;

    const int smem_bytes = SMEM_FLOATS * (int)sizeof(float);
    cudaFuncSetAttribute(lstm_persistent<0>, cudaFuncAttributeMaxDynamicSharedMemorySize, smem_bytes);
    cudaFuncSetAttribute(lstm_persistent<1>, cudaFuncAttributeMaxDynamicSharedMemorySize, smem_bytes);

    dim3 gemm_grid(GG / 128, (BB * TT) / 128);

    // ---- Layer 0 ----
    sgemm_input<1><<<gemm_grid, 256>>>(x, 0, DIN, DIN, W_ih0, b_ih0, b_hh0);
    zero_state_kernel<<<256, 256>>>();
    lstm_persistent<0><<<NCTA, 256, smem_bytes>>>(W_hh0, out);

    // ---- Layer 1 ----
    sgemm_input<0><<<gemm_grid, 256>>>(nullptr, 1, HH, HH, W_ih1, b_ih1, b_hh1);
    zero_state_kernel<<<256, 256>>>();
    lstm_persistent<1><<<NCTA, 256, smem_bytes>>>(W_hh1, out);
}

// round 4
// speedup vs baseline: 1.1924x; 1.1924x over previous
#include <cuda_runtime.h>
#include <cuda_bf16.h>
#include <math.h>
#include <stdint.h>

#define BB 64
#define TT 512
#define DIN 862
#define HH 1024
#define GG 4096

#define NCTA 128
#define CHUNK 128
#define NCHUNK (HH / CHUNK)   // 8

// ---------------- scratch (allocation-free rule: __device__ globals) ----------------
static __device__ float g_xg[(size_t)TT * BB * GG];          // [T*B][G] gate preactivations
static __device__ float g_h1[(size_t)TT * BB * HH];          // layer-0 output, rows m = t*B+b
static __device__ float g_hT[2][HH * BB];                    // transposed h state [j][b], ping-pong
static __device__ unsigned g_gen;
static __device__ unsigned g_cnt;
static __device__ __nv_bfloat16 g_Ahi[(size_t)TT * BB * 1024];
static __device__ __nv_bfloat16 g_Alo[(size_t)TT * BB * 1024];
static __device__ __nv_bfloat16 g_Whi[(size_t)GG * 1024];
static __device__ __nv_bfloat16 g_Wlo[(size_t)GG * 1024];

// ---------------- PTX helpers ----------------
__device__ __forceinline__ uint32_t smem_u32(const void* p) {
    uint32_t a;
    asm("{ .reg .u64 t; cvta.to.shared.u64 t, %1; cvt.u32.u64 %0, t; }" : "=r"(a) : "l"(p));
    return a;
}
__device__ __forceinline__ void cp_async16(uint32_t dst, const void* src) {
    asm volatile("cp.async.cg.shared.global [%0], [%1], 16;" :: "r"(dst), "l"(src));
}
__device__ __forceinline__ void cp_commit() { asm volatile("cp.async.commit_group;" ::: "memory"); }
template<int N> __device__ __forceinline__ void cp_wait() { asm volatile("cp.async.wait_group %0;" :: "n"(N) : "memory"); }

#define LDSM4(r, addr) \
    asm volatile("ldmatrix.sync.aligned.m8n8.x4.shared.b16 {%0,%1,%2,%3}, [%4];" \
        : "=r"((r)[0]), "=r"((r)[1]), "=r"((r)[2]), "=r"((r)[3]) : "r"(addr))

#define MMA16816(c, a, b) \
    asm volatile("mma.sync.aligned.m16n8k16.row.col.f32.bf16.bf16.f32 " \
        "{%0,%1,%2,%3}, {%4,%5,%6,%7}, {%8,%9}, {%0,%1,%2,%3};" \
        : "+f"((c)[0]), "+f"((c)[1]), "+f"((c)[2]), "+f"((c)[3]) \
        : "r"((a)[0]), "r"((a)[1]), "r"((a)[2]), "r"((a)[3]), "r"((b)[0]), "r"((b)[1]))

// ---------------- fp32 -> split bf16 conversion ----------------
// mode 0: W [G][K] -> hi/lo [G][1024], zero-padded
// mode 1: x [B][T][DIN], row m=t*B+b -> A [32768][1024]
// mode 2: g_h1 [32768][1024] -> A
__global__ void conv_split(const float* __restrict__ src, int K, int mode) {
    size_t i = (size_t)blockIdx.x * blockDim.x + threadIdx.x;
    size_t total = (mode == 0) ? ((size_t)GG << 10) : ((size_t)TT * BB << 10);
    if (i >= total) return;
    int k = (int)(i & 1023);
    size_t row = i >> 10;
    float v = 0.f;
    if (k < K) {
        if (mode == 1) {
            int t = (int)(row >> 6), b = (int)(row & 63);
            v = src[((size_t)b * TT + t) * DIN + k];
        } else if (mode == 2) {
            v = g_h1[(row << 10) + k];
        } else {
            v = src[row * K + k];
        }
    }
    __nv_bfloat16 h = __float2bfloat16(v);
    __nv_bfloat16 l = __float2bfloat16(v - __bfloat162float(h));
    if (mode == 0) { g_Whi[i] = h; g_Wlo[i] = l; }
    else           { g_Ahi[i] = h; g_Alo[i] = l; }
}

// ---------------- mma.sync bf16 split GEMM ----------------
// C[m][n] = sum_k A[m][k]*W[n][k] + bias; M=32768, N=4096, K=1024 (padded).
// CTA: 128x128 tile, 8 warps (2m x 4n -> 64x32/warp). k-chunks of 64 bf16.
// SMEM tile rows: 64 bf16 = 128B data + 16B pad = 144B stride (conflict-free ldmatrix).
#define TROW 144
#define TILE_B (128 * TROW)       // 18432
#define STAGE_B (4 * TILE_B)      // Ahi, Alo, Whi, Wlo
#define GEMM_SMEM (2 * STAGE_B + 512)

__device__ __forceinline__ void gemm_issue_loads(uint32_t sbase, int c, int m0, int n0, int tid) {
    const __nv_bfloat16* ptrs[4] = { g_Ahi, g_Alo, g_Whi, g_Wlo };
#pragma unroll
    for (int q = 0; q < 4; q++) {
        const __nv_bfloat16* p = ptrs[q];
        int rowbase = (q < 2) ? m0 : n0;
        uint32_t tb = sbase + q * TILE_B;
#pragma unroll
        for (int i = 0; i < 4; i++) {
            int idx = tid + i * 256;          // 0..1023: 128 rows x 8 x 16B
            int r = idx >> 3, s = idx & 7;
            cp_async16(tb + r * TROW + s * 16,
                       p + (((size_t)(rowbase + r)) << 10) + (c << 6) + (s << 3));
        }
    }
}

__global__ void __launch_bounds__(256, 1)
gemm_bf16_split(const float* __restrict__ b1, const float* __restrict__ b2)
{
    extern __shared__ char smraw[];
    uint32_t sbase = smem_u32(smraw);
    float* sbias = (float*)(smraw + 2 * STAGE_B);

    const int tid = threadIdx.x;
    const int lane = tid & 31, wid = tid >> 5;
    const int n0 = blockIdx.x * 128;
    const int m0 = blockIdx.y * 128;
    const int wm = (wid >> 2) * 64;    // warp m-offset within tile
    const int wn = (wid & 3) * 32;     // warp n-offset within tile

    if (tid < 128) sbias[tid] = b1[n0 + tid] + b2[n0 + tid];

    float acc[4][4][4];
#pragma unroll
    for (int i = 0; i < 4; i++)
#pragma unroll
        for (int j = 0; j < 4; j++)
#pragma unroll
            for (int q = 0; q < 4; q++) acc[i][j][q] = 0.f;

    gemm_issue_loads(sbase, 0, m0, n0, tid);
    cp_commit();

    // ldmatrix address components (constant across chunks)
    const uint32_t a_row = wm + (lane & 15);            // A: rows 0-15 of mtile
    const uint32_t a_coh = (lane >> 4) << 4;            // byte offset of k-half (8 bf16)
    const uint32_t b_rlo = (lane >> 4) * 8 + (lane & 7);  // W: n row within 16-group
    const uint32_t b_coh = ((lane >> 3) & 1) << 4;

    for (int c = 0; c < 16; c++) {
        if (c < 15) {
            gemm_issue_loads(sbase + ((c + 1) & 1) * STAGE_B, c + 1, m0, n0, tid);
            cp_commit();
            cp_wait<1>();
        } else {
            cp_wait<0>();
        }
        __syncthreads();

        const uint32_t buf = sbase + (c & 1) * STAGE_B;
        const uint32_t Ahi_b = buf;
        const uint32_t Alo_b = buf + TILE_B;
        const uint32_t Whi_b = buf + 2 * TILE_B;
        const uint32_t Wlo_b = buf + 3 * TILE_B;

#pragma unroll
        for (int ks = 0; ks < 4; ks++) {
            const uint32_t kso = ks * 32;   // bytes: 16 bf16 per k-step

            uint32_t ah[4][4], bh[4][2];
#pragma unroll
            for (int mt = 0; mt < 4; mt++)
                LDSM4(ah[mt], Ahi_b + (a_row + mt * 16) * TROW + kso + a_coh);
#pragma unroll
            for (int g = 0; g < 2; g++) {
                uint32_t t4[4];
                LDSM4(t4, Whi_b + (wn + g * 16 + b_rlo) * TROW + kso + b_coh);
                bh[g * 2][0] = t4[0]; bh[g * 2][1] = t4[1];
                bh[g * 2 + 1][0] = t4[2]; bh[g * 2 + 1][1] = t4[3];
            }
#pragma unroll
            for (int mt = 0; mt < 4; mt++)
#pragma unroll
                for (int nt = 0; nt < 4; nt++)
                    MMA16816(acc[mt][nt], ah[mt], bh[nt]);

            // hi * lo
            uint32_t bl[4][2];
#pragma unroll
            for (int g = 0; g < 2; g++) {
                uint32_t t4[4];
                LDSM4(t4, Wlo_b + (wn + g * 16 + b_rlo) * TROW + kso + b_coh);
                bl[g * 2][0] = t4[0]; bl[g * 2][1] = t4[1];
                bl[g * 2 + 1][0] = t4[2]; bl[g * 2 + 1][1] = t4[3];
            }
#pragma unroll
            for (int mt = 0; mt < 4; mt++)
#pragma unroll
                for (int nt = 0; nt < 4; nt++)
                    MMA16816(acc[mt][nt], ah[mt], bl[nt]);

            // lo * hi
            uint32_t al[4][4];
#pragma unroll
            for (int mt = 0; mt < 4; mt++)
                LDSM4(al[mt], Alo_b + (a_row + mt * 16) * TROW + kso + a_coh);
#pragma unroll
            for (int mt = 0; mt < 4; mt++)
#pragma unroll
                for (int nt = 0; nt < 4; nt++)
                    MMA16816(acc[mt][nt], al[mt], bh[nt]);
        }
        __syncthreads();
    }

    // epilogue: acc regs -> g_xg with bias
    const int r_lo = lane >> 2;
    const int cpos = (lane & 3) * 2;
#pragma unroll
    for (int mt = 0; mt < 4; mt++) {
        int row0 = m0 + wm + mt * 16 + r_lo;
#pragma unroll
        for (int nt = 0; nt < 4; nt++) {
            int cl = wn + nt * 8 + cpos;
            float bx = sbias[cl], by = sbias[cl + 1];
            float2 v0 = make_float2(acc[mt][nt][0] + bx, acc[mt][nt][1] + by);
            float2 v1 = make_float2(acc[mt][nt][2] + bx, acc[mt][nt][3] + by);
            *(float2*)&g_xg[(size_t)row0 * GG + n0 + cl] = v0;
            *(float2*)&g_xg[(size_t)(row0 + 8) * GG + n0 + cl] = v1;
        }
    }
}

// ---------------- recurrence (unchanged from passing round 2) ----------------
__global__ void zero_state_kernel() {
    int i = blockIdx.x * blockDim.x + threadIdx.x;
    if (i == 0) { g_gen = 0u; g_cnt = 0u; }
    const int n = 2 * HH * BB;
    for (; i < n; i += gridDim.x * blockDim.x) ((float*)g_hT)[i] = 0.f;
}

#define SMEM_FLOATS (32 * 1028 + 2 * CHUNK * 64 + 32 * 64 + 8 * 64)

template<int LAYER>
__global__ void __launch_bounds__(256, 1)
lstm_persistent(const float* __restrict__ W_hh, float* __restrict__ out_ext)
{
    extern __shared__ float sm[];
    float* ws = sm;                       // [32][1028]
    float* hs = ws + 32 * 1028;           // 2 x [128][64]
    float* ab = hs + 2 * CHUNK * 64;      // [32][64]
    float* cs = ab + 32 * 64;             // [512]

    const int tid = threadIdx.x;
    const int j0 = blockIdx.x * 8;

#pragma unroll 4
    for (int i = 0; i < 32; i++) {
        int grow = ((i & 3) << 10) + j0 + (i >> 2);
        float4 v = *(const float4*)(W_hh + (size_t)grow * HH + tid * 4);
        *(float4*)&ws[i * 1028 + tid * 4] = v;
    }
    for (int i = tid; i < 512; i += 256) cs[i] = 0.f;
    __syncthreads();

    const int w  = tid >> 5;
    const int lr = (tid >> 3) & 3;
    const int lc = tid & 7;
    const int rr0 = (w >> 1) * 8 + lr * 2;
    const int b0  = (w & 1) * 32 + lc * 4;
    const float* w0p = ws + rr0 * 1028;
    const float* w1p = w0p + 1028;

    unsigned gen = 0;

    for (int t = 0; t < TT; t++) {
        const float* hin  = g_hT[t & 1];
        float*       hout = g_hT[(t + 1) & 1];

        {
            const float4* src = (const float4*)hin;
            float4* dst = (float4*)hs;
#pragma unroll
            for (int i = 0; i < 8; i++) dst[tid + i * 256] = src[tid + i * 256];
        }
        __syncthreads();

        float4 acc0 = make_float4(0.f, 0.f, 0.f, 0.f);
        float4 acc1 = make_float4(0.f, 0.f, 0.f, 0.f);

        for (int c = 0; c < NCHUNK; c++) {
            const int cb = c & 1;
            if (c < NCHUNK - 1) {
                const float4* src = (const float4*)(hin + (c + 1) * CHUNK * 64);
                float4* dst = (float4*)(hs + (cb ^ 1) * (CHUNK * 64));
#pragma unroll
                for (int i = 0; i < 8; i++) dst[tid + i * 256] = src[tid + i * 256];
            }
            const float* hc = hs + cb * (CHUNK * 64);
            const int kbase = c * CHUNK;
#pragma unroll 8
            for (int kk = 0; kk < CHUNK; kk += 4) {
                float4 w0 = *(const float4*)(w0p + kbase + kk);
                float4 w1 = *(const float4*)(w1p + kbase + kk);
                float4 h0 = *(const float4*)(hc + (kk + 0) * 64 + b0);
                float4 h1 = *(const float4*)(hc + (kk + 1) * 64 + b0);
                float4 h2 = *(const float4*)(hc + (kk + 2) * 64 + b0);
                float4 h3 = *(const float4*)(hc + (kk + 3) * 64 + b0);
                acc0.x = fmaf(w0.x, h0.x, acc0.x); acc0.y = fmaf(w0.x, h0.y, acc0.y);
                acc0.z = fmaf(w0.x, h0.z, acc0.z); acc0.w = fmaf(w0.x, h0.w, acc0.w);
                acc0.x = fmaf(w0.y, h1.x, acc0.x); acc0.y = fmaf(w0.y, h1.y, acc0.y);
                acc0.z = fmaf(w0.y, h1.z, acc0.z); acc0.w = fmaf(w0.y, h1.w, acc0.w);
                acc0.x = fmaf(w0.z, h2.x, acc0.x); acc0.y = fmaf(w0.z, h2.y, acc0.y);
                acc0.z = fmaf(w0.z, h2.z, acc0.z); acc0.w = fmaf(w0.z, h2.w, acc0.w);
                acc0.x = fmaf(w0.w, h3.x, acc0.x); acc0.y = fmaf(w0.w, h3.y, acc0.y);
                acc0.z = fmaf(w0.w, h3.z, acc0.z); acc0.w = fmaf(w0.w, h3.w, acc0.w);
                acc1.x = fmaf(w1.x, h0.x, acc1.x); acc1.y = fmaf(w1.x, h0.y, acc1.y);
                acc1.z = fmaf(w1.x, h0.z, acc1.z); acc1.w = fmaf(w1.x, h0.w, acc1.w);
                acc1.x = fmaf(w1.y, h1.x, acc1.x); acc1.y = fmaf(w1.y, h1.y, acc1.y);
                acc1.z = fmaf(w1.y, h1.z, acc1.z); acc1.w = fmaf(w1.y, h1.w, acc1.w);
                acc1.x = fmaf(w1.z, h2.x, acc1.x); acc1.y = fmaf(w1.z, h2.y, acc1.y);
                acc1.z = fmaf(w1.z, h2.z, acc1.z); acc1.w = fmaf(w1.z, h2.w, acc1.w);
                acc1.x = fmaf(w1.w, h3.x, acc1.x); acc1.y = fmaf(w1.w, h3.y, acc1.y);
                acc1.z = fmaf(w1.w, h3.z, acc1.z); acc1.w = fmaf(w1.w, h3.w, acc1.w);
            }
            __syncthreads();
        }

        *(float4*)&ab[rr0 * 64 + b0] = acc0;
        *(float4*)&ab[(rr0 + 1) * 64 + b0] = acc1;
        __syncthreads();

#pragma unroll
        for (int u = 0; u < 2; u++) {
            int cell = tid + u * 256;
            int jj = cell >> 6, b = cell & 63;
            size_t xbase = ((size_t)t * BB + b) * GG + j0 + jj;
            float pi = ab[(jj * 4 + 0) * 64 + b] + g_xg[xbase];
            float pf = ab[(jj * 4 + 1) * 64 + b] + g_xg[xbase + 1024];
            float pg = ab[(jj * 4 + 2) * 64 + b] + g_xg[xbase + 2048];
            float po = ab[(jj * 4 + 3) * 64 + b] + g_xg[xbase + 3072];
            float ig = 1.f / (1.f + expf(-pi));
            float fg = 1.f / (1.f + expf(-pf));
            float gc = tanhf(pg);
            float og = 1.f / (1.f + expf(-po));
            float cn = fg * cs[cell] + ig * gc;
            float hn = og * tanhf(cn);
            cs[cell] = cn;
            hout[(j0 + jj) * 64 + b] = hn;
            if (LAYER == 0) g_h1[((size_t)t * BB + b) * HH + j0 + jj] = hn;
            else            out_ext[((size_t)b * TT + t) * HH + j0 + jj] = hn;
        }

        __threadfence();
        __syncthreads();
        gen++;
        if (tid == 0) {
            if (atomicAdd(&g_cnt, 1u) == NCTA - 1) {
                g_cnt = 0u;
                __threadfence();
                *(volatile unsigned*)&g_gen = gen;
            } else {
                while (*(volatile unsigned*)&g_gen < gen) { }
                __threadfence();
            }
        }
        __syncthreads();
    }
}

// ---------------- launch ----------------
extern "C" void kernel_launch(void* const* d_in, const int* in_sizes, int n_in,
                              void* d_out, int out_size)
{
    (void)in_sizes; (void)n_in; (void)out_size;
    const float* x     = (const float*)d_in[0];
    const float* W_ih0 = (const float*)d_in[1];
    const float* W_hh0 = (const float*)d_in[2];
    const float* b_ih0 = (const float*)d_in[3];
    const float* b_hh0 = (const float*)d_in[4];
    const float* W_ih1 = (const float*)d_in[5];
    const float* W_hh1 = (const float*)d_in[6];
    const float* b_ih1 = (const float*)d_in[7];
    const float* b_hh1 = (const float*)d_in[8];
    float* out = (float*)d_out;

    const int rec_smem = SMEM_FLOATS * (int)sizeof(float);
    cudaFuncSetAttribute(lstm_persistent<0>, cudaFuncAttributeMaxDynamicSharedMemorySize, rec_smem);
    cudaFuncSetAttribute(lstm_persistent<1>, cudaFuncAttributeMaxDynamicSharedMemorySize, rec_smem);
    cudaFuncSetAttribute(gemm_bf16_split, cudaFuncAttributeMaxDynamicSharedMemorySize, GEMM_SMEM);

    const size_t convW_n = (size_t)GG * 1024;
    const size_t convA_n = (size_t)TT * BB * 1024;
    dim3 gemm_grid(GG / 128, (TT * BB) / 128);

    // ---- Layer 0 ----
    conv_split<<<(int)((convW_n + 255) / 256), 256>>>(W_ih0, DIN, 0);
    conv_split<<<(int)((convA_n + 255) / 256), 256>>>(x, DIN, 1);
    gemm_bf16_split<<<gemm_grid, 256, GEMM_SMEM>>>(b_ih0, b_hh0);
    zero_state_kernel<<<256, 256>>>();
    lstm_persistent<0><<<NCTA, 256, rec_smem>>>(W_hh0, out);

    // ---- Layer 1 ----
    conv_split<<<(int)((convW_n + 255) / 256), 256>>>(W_ih1, HH, 0);
    conv_split<<<(int)((convA_n + 255) / 256), 256>>>(nullptr, HH, 2);
    gemm_bf16_split<<<gemm_grid, 256, GEMM_SMEM>>>(b_ih1, b_hh1);
    zero_state_kernel<<<256, 256>>>();
    lstm_persistent<1><<<NCTA, 256, rec_smem>>>(W_hh1, out);
}

// round 5
// speedup vs baseline: 2.7049x; 2.2683x over previous
#include <cuda_runtime.h>
#include <cuda_bf16.h>
#include <math.h>
#include <stdint.h>

#define BB 64
#define TT 512
#define DIN 862
#define HH 1024
#define GG 4096

#define NCTA 128

// ---------------- scratch (allocation-free rule: __device__ globals) ----------------
static __device__ float g_xg[(size_t)TT * BB * GG];          // [T*B][G] gate preactivations
static __device__ float g_h1[(size_t)TT * BB * HH];          // layer-0 output, rows m = t*B+b
static __device__ unsigned g_gen;
static __device__ unsigned g_cnt;
static __device__ __nv_bfloat16 g_Ahi[(size_t)TT * BB * 1024];
static __device__ __nv_bfloat16 g_Alo[(size_t)TT * BB * 1024];
static __device__ __nv_bfloat16 g_Whi[(size_t)GG * 1024];
static __device__ __nv_bfloat16 g_Wlo[(size_t)GG * 1024];
static __device__ __nv_bfloat16 g_ghi[2][BB * HH];           // h state bf16 hi, ping-pong [b][k]
static __device__ __nv_bfloat16 g_glo[2][BB * HH];           // h state bf16 lo

// ---------------- PTX helpers ----------------
__device__ __forceinline__ uint32_t smem_u32(const void* p) {
    uint32_t a;
    asm("{ .reg .u64 t; cvta.to.shared.u64 t, %1; cvt.u32.u64 %0, t; }" : "=r"(a) : "l"(p));
    return a;
}
__device__ __forceinline__ void cp_async16(uint32_t dst, const void* src) {
    asm volatile("cp.async.cg.shared.global [%0], [%1], 16;" :: "r"(dst), "l"(src));
}
__device__ __forceinline__ void cp_commit() { asm volatile("cp.async.commit_group;" ::: "memory"); }
template<int N> __device__ __forceinline__ void cp_wait() { asm volatile("cp.async.wait_group %0;" :: "n"(N) : "memory"); }

#define LDSM4(r, addr) \
    asm volatile("ldmatrix.sync.aligned.m8n8.x4.shared.b16 {%0,%1,%2,%3}, [%4];" \
        : "=r"((r)[0]), "=r"((r)[1]), "=r"((r)[2]), "=r"((r)[3]) : "r"(addr))

#define MMA16816(c, a, b) \
    asm volatile("mma.sync.aligned.m16n8k16.row.col.f32.bf16.bf16.f32 " \
        "{%0,%1,%2,%3}, {%4,%5,%6,%7}, {%8,%9}, {%0,%1,%2,%3};" \
        : "+f"((c)[0]), "+f"((c)[1]), "+f"((c)[2]), "+f"((c)[3]) \
        : "r"((a)[0]), "r"((a)[1]), "r"((a)[2]), "r"((a)[3]), "r"((b)[0]), "r"((b)[1]))

// ---------------- fp32 -> split bf16 conversion ----------------
// mode 0: W [G][K] -> hi/lo [G][1024], zero-padded
// mode 1: x [B][T][DIN], row m=t*B+b -> A [32768][1024]
// mode 2: g_h1 [32768][1024] -> A
__global__ void conv_split(const float* __restrict__ src, int K, int mode) {
    size_t i = (size_t)blockIdx.x * blockDim.x + threadIdx.x;
    size_t total = (mode == 0) ? ((size_t)GG << 10) : ((size_t)TT * BB << 10);
    if (i >= total) return;
    int k = (int)(i & 1023);
    size_t row = i >> 10;
    float v = 0.f;
    if (k < K) {
        if (mode == 1) {
            int t = (int)(row >> 6), b = (int)(row & 63);
            v = src[((size_t)b * TT + t) * DIN + k];
        } else if (mode == 2) {
            v = g_h1[(row << 10) + k];
        } else {
            v = src[row * K + k];
        }
    }
    __nv_bfloat16 h = __float2bfloat16(v);
    __nv_bfloat16 l = __float2bfloat16(v - __bfloat162float(h));
    if (mode == 0) { g_Whi[i] = h; g_Wlo[i] = l; }
    else           { g_Ahi[i] = h; g_Alo[i] = l; }
}

// ---------------- mma.sync bf16 split GEMM (unchanged, passing) ----------------
#define TROW 144
#define TILE_B (128 * TROW)
#define STAGE_B (4 * TILE_B)
#define GEMM_SMEM (2 * STAGE_B + 512)

__device__ __forceinline__ void gemm_issue_loads(uint32_t sbase, int c, int m0, int n0, int tid) {
    const __nv_bfloat16* ptrs[4] = { g_Ahi, g_Alo, g_Whi, g_Wlo };
#pragma unroll
    for (int q = 0; q < 4; q++) {
        const __nv_bfloat16* p = ptrs[q];
        int rowbase = (q < 2) ? m0 : n0;
        uint32_t tb = sbase + q * TILE_B;
#pragma unroll
        for (int i = 0; i < 4; i++) {
            int idx = tid + i * 256;
            int r = idx >> 3, s = idx & 7;
            cp_async16(tb + r * TROW + s * 16,
                       p + (((size_t)(rowbase + r)) << 10) + (c << 6) + (s << 3));
        }
    }
}

__global__ void __launch_bounds__(256, 1)
gemm_bf16_split(const float* __restrict__ b1, const float* __restrict__ b2)
{
    extern __shared__ char smraw[];
    uint32_t sbase = smem_u32(smraw);
    float* sbias = (float*)(smraw + 2 * STAGE_B);

    const int tid = threadIdx.x;
    const int lane = tid & 31, wid = tid >> 5;
    const int n0 = blockIdx.x * 128;
    const int m0 = blockIdx.y * 128;
    const int wm = (wid >> 2) * 64;
    const int wn = (wid & 3) * 32;

    if (tid < 128) sbias[tid] = b1[n0 + tid] + b2[n0 + tid];

    float acc[4][4][4];
#pragma unroll
    for (int i = 0; i < 4; i++)
#pragma unroll
        for (int j = 0; j < 4; j++)
#pragma unroll
            for (int q = 0; q < 4; q++) acc[i][j][q] = 0.f;

    gemm_issue_loads(sbase, 0, m0, n0, tid);
    cp_commit();

    const uint32_t a_row = wm + (lane & 15);
    const uint32_t a_coh = (lane >> 4) << 4;
    const uint32_t b_rlo = (lane >> 4) * 8 + (lane & 7);
    const uint32_t b_coh = ((lane >> 3) & 1) << 4;

    for (int c = 0; c < 16; c++) {
        if (c < 15) {
            gemm_issue_loads(sbase + ((c + 1) & 1) * STAGE_B, c + 1, m0, n0, tid);
            cp_commit();
            cp_wait<1>();
        } else {
            cp_wait<0>();
        }
        __syncthreads();

        const uint32_t buf = sbase + (c & 1) * STAGE_B;
        const uint32_t Ahi_b = buf;
        const uint32_t Alo_b = buf + TILE_B;
        const uint32_t Whi_b = buf + 2 * TILE_B;
        const uint32_t Wlo_b = buf + 3 * TILE_B;

#pragma unroll
        for (int ks = 0; ks < 4; ks++) {
            const uint32_t kso = ks * 32;
            uint32_t ah[4][4], bh[4][2];
#pragma unroll
            for (int mt = 0; mt < 4; mt++)
                LDSM4(ah[mt], Ahi_b + (a_row + mt * 16) * TROW + kso + a_coh);
#pragma unroll
            for (int g = 0; g < 2; g++) {
                uint32_t t4[4];
                LDSM4(t4, Whi_b + (wn + g * 16 + b_rlo) * TROW + kso + b_coh);
                bh[g * 2][0] = t4[0]; bh[g * 2][1] = t4[1];
                bh[g * 2 + 1][0] = t4[2]; bh[g * 2 + 1][1] = t4[3];
            }
#pragma unroll
            for (int mt = 0; mt < 4; mt++)
#pragma unroll
                for (int nt = 0; nt < 4; nt++)
                    MMA16816(acc[mt][nt], ah[mt], bh[nt]);

            uint32_t bl[4][2];
#pragma unroll
            for (int g = 0; g < 2; g++) {
                uint32_t t4[4];
                LDSM4(t4, Wlo_b + (wn + g * 16 + b_rlo) * TROW + kso + b_coh);
                bl[g * 2][0] = t4[0]; bl[g * 2][1] = t4[1];
                bl[g * 2 + 1][0] = t4[2]; bl[g * 2 + 1][1] = t4[3];
            }
#pragma unroll
            for (int mt = 0; mt < 4; mt++)
#pragma unroll
                for (int nt = 0; nt < 4; nt++)
                    MMA16816(acc[mt][nt], ah[mt], bl[nt]);

            uint32_t al[4][4];
#pragma unroll
            for (int mt = 0; mt < 4; mt++)
                LDSM4(al[mt], Alo_b + (a_row + mt * 16) * TROW + kso + a_coh);
#pragma unroll
            for (int mt = 0; mt < 4; mt++)
#pragma unroll
                for (int nt = 0; nt < 4; nt++)
                    MMA16816(acc[mt][nt], al[mt], bh[nt]);
        }
        __syncthreads();
    }

    const int r_lo = lane >> 2;
    const int cpos = (lane & 3) * 2;
#pragma unroll
    for (int mt = 0; mt < 4; mt++) {
        int row0 = m0 + wm + mt * 16 + r_lo;
#pragma unroll
        for (int nt = 0; nt < 4; nt++) {
            int cl = wn + nt * 8 + cpos;
            float bx = sbias[cl], by = sbias[cl + 1];
            float2 v0 = make_float2(acc[mt][nt][0] + bx, acc[mt][nt][1] + by);
            float2 v1 = make_float2(acc[mt][nt][2] + bx, acc[mt][nt][3] + by);
            *(float2*)&g_xg[(size_t)row0 * GG + n0 + cl] = v0;
            *(float2*)&g_xg[(size_t)(row0 + 8) * GG + n0 + cl] = v1;
        }
    }
}

// ---------------- tensor-core persistent recurrence ----------------
// 128 CTAs x 128 threads (4 warps). CTA owns 8 hidden units j0..j0+7 ->
// 32 gate rows (n = gate*8 + jl). W_hh hi/lo bf16 resident in smem.
// Per step: acc[64b x 32n] = h @ W^T via 3-pass bf16 split; c in registers.
// h broadcast via global bf16 hi/lo ping-pong [b][1024], staged in 8 chunks of 128 k.
#define WROW 2064                      // 1024 bf16 + 16B pad
#define WS_B (32 * WROW)               // 66048 per array
#define AROW 272                       // 128 bf16 + 16B pad
#define AT_B (64 * AROW)               // 17408 per array
#define ASTG (2 * AT_B)                // hi + lo per stage
#define REC_SMEM (2 * WS_B + 2 * ASTG) // 201728

__global__ void zero_rec() {
    int i = blockIdx.x * blockDim.x + threadIdx.x;
    if (i == 0) { g_gen = 0u; g_cnt = 0u; }
    uint32_t* p1 = (uint32_t*)g_ghi;
    uint32_t* p2 = (uint32_t*)g_glo;
    for (int k = i; k < 65536; k += gridDim.x * blockDim.x) { p1[k] = 0u; p2[k] = 0u; }
}

__device__ __forceinline__ void rec_stage(uint32_t dsthi, const __nv_bfloat16* ghi,
                                          const __nv_bfloat16* glo, int c, int tid) {
#pragma unroll
    for (int i = 0; i < 8; i++) {
        int idx = tid + i * 128;            // 0..1023
        int r = idx >> 4, s = idx & 15;     // 64 rows x 16 x 16B
        uint32_t d = dsthi + r * AROW + s * 16;
        size_t so = (size_t)r * 1024 + c * 128 + s * 8;
        cp_async16(d, ghi + so);
        cp_async16(d + AT_B, glo + so);
    }
}

template<int LAYER>
__global__ void __launch_bounds__(128, 1)
lstm_rec_tc(float* __restrict__ out_ext)
{
    extern __shared__ char smraw[];
    const uint32_t sb = smem_u32(smraw);
    const uint32_t ws_hi = sb;
    const uint32_t ws_lo = sb + WS_B;
    const uint32_t as0   = sb + 2 * WS_B;

    const int tid = threadIdx.x;
    const int lane = tid & 31, wid = tid >> 5;
    const int j0 = blockIdx.x * 8;

    // Load W_hh hi/lo (32 rows) into smem once
#pragma unroll 4
    for (int n = 0; n < 32; n++) {
        int grow = ((n >> 3) << 10) + j0 + (n & 7);
        cp_async16(ws_hi + n * WROW + tid * 16, g_Whi + ((size_t)grow << 10) + tid * 8);
        cp_async16(ws_lo + n * WROW + tid * 16, g_Wlo + ((size_t)grow << 10) + tid * 8);
    }
    cp_commit(); cp_wait<0>();
    __syncthreads();

    // fragment address constants
    const uint32_t a_off = (wid * 16 + (lane & 15)) * AROW + ((lane >> 4) << 4);
    const uint32_t w_off = ((lane >> 4) * 8 + (lane & 7)) * WROW + (((lane >> 3) & 1) << 4);

    // cell mapping (reuse-verified from GEMM epilogue):
    // acc[nt][0]=(r0,c0) [1]=(r0,c1) [2]=(r1,c0) [3]=(r1,c1); r1=r0+8; gate=nt
    const int r0 = lane >> 2;
    const int c0 = (lane & 3) * 2;
    const int bA = wid * 16 + r0;        // batch for q 0/1
    const int bB = bA + 8;               // batch for q 2/3
    const int jj = j0 + c0;

    float cst[4] = {0.f, 0.f, 0.f, 0.f}; // c state: [rp*2+cc]
    unsigned gen = 0;

    for (int t = 0; t < TT; t++) {
        const __nv_bfloat16* ghi_in = g_ghi[t & 1];
        const __nv_bfloat16* glo_in = g_glo[t & 1];
        __nv_bfloat16* ghi_out = g_ghi[(t + 1) & 1];
        __nv_bfloat16* glo_out = g_glo[(t + 1) & 1];

        // prefetch xg for this thread's cells
        float2 xgv[2][4];
#pragma unroll
        for (int rp = 0; rp < 2; rp++) {
            size_t base = ((size_t)t * BB + (rp ? bB : bA)) * GG + jj;
#pragma unroll
            for (int g = 0; g < 4; g++)
                xgv[rp][g] = *(const float2*)&g_xg[base + (size_t)g * HH];
        }

        float acc[4][4];
#pragma unroll
        for (int nt = 0; nt < 4; nt++)
#pragma unroll
            for (int q = 0; q < 4; q++) acc[nt][q] = 0.f;

        rec_stage(as0, ghi_in, glo_in, 0, tid);
        cp_commit();

        for (int c = 0; c < 8; c++) {
            if (c < 7) {
                rec_stage(as0 + ((c + 1) & 1) * ASTG, ghi_in, glo_in, c + 1, tid);
                cp_commit();
                cp_wait<1>();
            } else {
                cp_wait<0>();
            }
            __syncthreads();

            const uint32_t abuf = as0 + (c & 1) * ASTG;
#pragma unroll
            for (int kl = 0; kl < 8; kl++) {
                const uint32_t Aad = abuf + a_off + kl * 32;
                const uint32_t kby = (uint32_t)(c * 128 + kl * 16) * 2;

                uint32_t ah[4], al[4], bh[4][2], bl[4][2];
                LDSM4(ah, Aad);
                LDSM4(al, Aad + AT_B);
                {
                    uint32_t t4[4];
                    LDSM4(t4, ws_hi + w_off + kby);
                    bh[0][0] = t4[0]; bh[0][1] = t4[1]; bh[1][0] = t4[2]; bh[1][1] = t4[3];
                    LDSM4(t4, ws_hi + 16 * WROW + w_off + kby);
                    bh[2][0] = t4[0]; bh[2][1] = t4[1]; bh[3][0] = t4[2]; bh[3][1] = t4[3];
                    LDSM4(t4, ws_lo + w_off + kby);
                    bl[0][0] = t4[0]; bl[0][1] = t4[1]; bl[1][0] = t4[2]; bl[1][1] = t4[3];
                    LDSM4(t4, ws_lo + 16 * WROW + w_off + kby);
                    bl[2][0] = t4[0]; bl[2][1] = t4[1]; bl[3][0] = t4[2]; bl[3][1] = t4[3];
                }
#pragma unroll
                for (int nt = 0; nt < 4; nt++) {
                    MMA16816(acc[nt], ah, bh[nt]);
                    MMA16816(acc[nt], al, bh[nt]);
                    MMA16816(acc[nt], ah, bl[nt]);
                }
            }
            __syncthreads();
        }

        // pointwise LSTM update (thread-local cells)
#pragma unroll
        for (int rp = 0; rp < 2; rp++) {
            const int b = rp ? bB : bA;
            float hn[2];
#pragma unroll
            for (int cc = 0; cc < 2; cc++) {
                const int q = rp * 2 + cc;
                float pi = acc[0][q] + (cc ? xgv[rp][0].y : xgv[rp][0].x);
                float pf = acc[1][q] + (cc ? xgv[rp][1].y : xgv[rp][1].x);
                float pg = acc[2][q] + (cc ? xgv[rp][2].y : xgv[rp][2].x);
                float po = acc[3][q] + (cc ? xgv[rp][3].y : xgv[rp][3].x);
                float ig = 1.f / (1.f + expf(-pi));
                float fg = 1.f / (1.f + expf(-pf));
                float gc = tanhf(pg);
                float og = 1.f / (1.f + expf(-po));
                float cn = fg * cst[q] + ig * gc;
                cst[q] = cn;
                hn[cc] = og * tanhf(cn);
            }
            // split h -> bf16 hi/lo, write to ping-pong state
            __nv_bfloat16 h0 = __float2bfloat16(hn[0]);
            __nv_bfloat16 h1 = __float2bfloat16(hn[1]);
            __nv_bfloat16 l0 = __float2bfloat16(hn[0] - __bfloat162float(h0));
            __nv_bfloat16 l1 = __float2bfloat16(hn[1] - __bfloat162float(h1));
            *(__nv_bfloat162*)&ghi_out[(size_t)b * HH + jj] = __nv_bfloat162(h0, h1);
            *(__nv_bfloat162*)&glo_out[(size_t)b * HH + jj] = __nv_bfloat162(l0, l1);
            // fp32 layer output
            float2 hv = make_float2(hn[0], hn[1]);
            if (LAYER == 0) *(float2*)&g_h1[((size_t)t * BB + b) * HH + jj] = hv;
            else            *(float2*)&out_ext[((size_t)b * TT + t) * HH + jj] = hv;
        }

        // grid barrier
        __threadfence();
        __syncthreads();
        gen++;
        if (tid == 0) {
            if (atomicAdd(&g_cnt, 1u) == NCTA - 1) {
                g_cnt = 0u;
                __threadfence();
                *(volatile unsigned*)&g_gen = gen;
            } else {
                while (*(volatile unsigned*)&g_gen < gen) { }
                __threadfence();
            }
        }
        __syncthreads();
    }
}

// ---------------- launch ----------------
extern "C" void kernel_launch(void* const* d_in, const int* in_sizes, int n_in,
                              void* d_out, int out_size)
{
    (void)in_sizes; (void)n_in; (void)out_size;
    const float* x     = (const float*)d_in[0];
    const float* W_ih0 = (const float*)d_in[1];
    const float* W_hh0 = (const float*)d_in[2];
    const float* b_ih0 = (const float*)d_in[3];
    const float* b_hh0 = (const float*)d_in[4];
    const float* W_ih1 = (const float*)d_in[5];
    const float* W_hh1 = (const float*)d_in[6];
    const float* b_ih1 = (const float*)d_in[7];
    const float* b_hh1 = (const float*)d_in[8];
    float* out = (float*)d_out;

    cudaFuncSetAttribute(gemm_bf16_split, cudaFuncAttributeMaxDynamicSharedMemorySize, GEMM_SMEM);
    cudaFuncSetAttribute(lstm_rec_tc<0>, cudaFuncAttributeMaxDynamicSharedMemorySize, REC_SMEM);
    cudaFuncSetAttribute(lstm_rec_tc<1>, cudaFuncAttributeMaxDynamicSharedMemorySize, REC_SMEM);

    const size_t convW_n = (size_t)GG * 1024;
    const size_t convA_n = (size_t)TT * BB * 1024;
    dim3 gemm_grid(GG / 128, (TT * BB) / 128);

    // ---- Layer 0 ----
    conv_split<<<(int)((convW_n + 255) / 256), 256>>>(W_ih0, DIN, 0);
    conv_split<<<(int)((convA_n + 255) / 256), 256>>>(x, DIN, 1);
    gemm_bf16_split<<<gemm_grid, 256, GEMM_SMEM>>>(b_ih0, b_hh0);
    conv_split<<<(int)((convW_n + 255) / 256), 256>>>(W_hh0, HH, 0);   // W_hh0 -> g_Whi/g_Wlo
    zero_rec<<<256, 256>>>();
    lstm_rec_tc<0><<<NCTA, 128, REC_SMEM>>>(out);

    // ---- Layer 1 ----
    conv_split<<<(int)((convW_n + 255) / 256), 256>>>(W_ih1, HH, 0);
    conv_split<<<(int)((convA_n + 255) / 256), 256>>>(nullptr, HH, 2);
    gemm_bf16_split<<<gemm_grid, 256, GEMM_SMEM>>>(b_ih1, b_hh1);
    conv_split<<<(int)((convW_n + 255) / 256), 256>>>(W_hh1, HH, 0);   // W_hh1 -> g_Whi/g_Wlo
    zero_rec<<<256, 256>>>();
    lstm_rec_tc<1><<<NCTA, 128, REC_SMEM>>>(out);
}

// round 6
// speedup vs baseline: 2.8775x; 1.0638x over previous
#include <cuda_runtime.h>
#include <cuda_bf16.h>
#include <math.h>
#include <stdint.h>

#define BB 64
#define TT 512
#define DIN 862
#define HH 1024
#define GG 4096

#define NCTA 128

// ---------------- scratch (allocation-free rule: __device__ globals) ----------------
static __device__ float g_xg[(size_t)TT * BB * GG];          // [T*B][G] gate preactivations
static __device__ float g_h1[(size_t)TT * BB * HH];          // layer-0 output, rows m = t*B+b
static __device__ unsigned g_gen;
static __device__ unsigned g_cnt;
static __device__ __nv_bfloat16 g_Ahi[(size_t)TT * BB * 1024];
static __device__ __nv_bfloat16 g_Alo[(size_t)TT * BB * 1024];
static __device__ __nv_bfloat16 g_Whi[(size_t)GG * 1024];
static __device__ __nv_bfloat16 g_Wlo[(size_t)GG * 1024];
static __device__ __nv_bfloat16 g_ghi[2][BB * HH];           // h state bf16 hi, ping-pong [b][k]
static __device__ __nv_bfloat16 g_glo[2][BB * HH];           // h state bf16 lo

// ---------------- PTX helpers ----------------
__device__ __forceinline__ uint32_t smem_u32(const void* p) {
    uint32_t a;
    asm("{ .reg .u64 t; cvta.to.shared.u64 t, %1; cvt.u32.u64 %0, t; }" : "=r"(a) : "l"(p));
    return a;
}
__device__ __forceinline__ void cp_async16(uint32_t dst, const void* src) {
    asm volatile("cp.async.cg.shared.global [%0], [%1], 16;" :: "r"(dst), "l"(src));
}
__device__ __forceinline__ void cp_commit() { asm volatile("cp.async.commit_group;" ::: "memory"); }
template<int N> __device__ __forceinline__ void cp_wait() { asm volatile("cp.async.wait_group %0;" :: "n"(N) : "memory"); }

#define LDSM4(r, addr) \
    asm volatile("ldmatrix.sync.aligned.m8n8.x4.shared.b16 {%0,%1,%2,%3}, [%4];" \
        : "=r"((r)[0]), "=r"((r)[1]), "=r"((r)[2]), "=r"((r)[3]) : "r"(addr))

#define MMA16816(c, a, b) \
    asm volatile("mma.sync.aligned.m16n8k16.row.col.f32.bf16.bf16.f32 " \
        "{%0,%1,%2,%3}, {%4,%5,%6,%7}, {%8,%9}, {%0,%1,%2,%3};" \
        : "+f"((c)[0]), "+f"((c)[1]), "+f"((c)[2]), "+f"((c)[3]) \
        : "r"((a)[0]), "r"((a)[1]), "r"((a)[2]), "r"((a)[3]), "r"((b)[0]), "r"((b)[1]))

// ---------------- fp32 -> split bf16 conversion ----------------
__global__ void conv_split(const float* __restrict__ src, int K, int mode) {
    size_t i = (size_t)blockIdx.x * blockDim.x + threadIdx.x;
    size_t total = (mode == 0) ? ((size_t)GG << 10) : ((size_t)TT * BB << 10);
    if (i >= total) return;
    int k = (int)(i & 1023);
    size_t row = i >> 10;
    float v = 0.f;
    if (k < K) {
        if (mode == 1) {
            int t = (int)(row >> 6), b = (int)(row & 63);
            v = src[((size_t)b * TT + t) * DIN + k];
        } else if (mode == 2) {
            v = g_h1[(row << 10) + k];
        } else {
            v = src[row * K + k];
        }
    }
    __nv_bfloat16 h = __float2bfloat16(v);
    __nv_bfloat16 l = __float2bfloat16(v - __bfloat162float(h));
    if (mode == 0) { g_Whi[i] = h; g_Wlo[i] = l; }
    else           { g_Ahi[i] = h; g_Alo[i] = l; }
}

// ---------------- mma.sync bf16 split GEMM (unchanged, passing) ----------------
#define TROW 144
#define TILE_B (128 * TROW)
#define STAGE_B (4 * TILE_B)
#define GEMM_SMEM (2 * STAGE_B + 512)

__device__ __forceinline__ void gemm_issue_loads(uint32_t sbase, int c, int m0, int n0, int tid) {
    const __nv_bfloat16* ptrs[4] = { g_Ahi, g_Alo, g_Whi, g_Wlo };
#pragma unroll
    for (int q = 0; q < 4; q++) {
        const __nv_bfloat16* p = ptrs[q];
        int rowbase = (q < 2) ? m0 : n0;
        uint32_t tb = sbase + q * TILE_B;
#pragma unroll
        for (int i = 0; i < 4; i++) {
            int idx = tid + i * 256;
            int r = idx >> 3, s = idx & 7;
            cp_async16(tb + r * TROW + s * 16,
                       p + (((size_t)(rowbase + r)) << 10) + (c << 6) + (s << 3));
        }
    }
}

__global__ void __launch_bounds__(256, 1)
gemm_bf16_split(const float* __restrict__ b1, const float* __restrict__ b2)
{
    extern __shared__ char smraw[];
    uint32_t sbase = smem_u32(smraw);
    float* sbias = (float*)(smraw + 2 * STAGE_B);

    const int tid = threadIdx.x;
    const int lane = tid & 31, wid = tid >> 5;
    const int n0 = blockIdx.x * 128;
    const int m0 = blockIdx.y * 128;
    const int wm = (wid >> 2) * 64;
    const int wn = (wid & 3) * 32;

    if (tid < 128) sbias[tid] = b1[n0 + tid] + b2[n0 + tid];

    float acc[4][4][4];
#pragma unroll
    for (int i = 0; i < 4; i++)
#pragma unroll
        for (int j = 0; j < 4; j++)
#pragma unroll
            for (int q = 0; q < 4; q++) acc[i][j][q] = 0.f;

    gemm_issue_loads(sbase, 0, m0, n0, tid);
    cp_commit();

    const uint32_t a_row = wm + (lane & 15);
    const uint32_t a_coh = (lane >> 4) << 4;
    const uint32_t b_rlo = (lane >> 4) * 8 + (lane & 7);
    const uint32_t b_coh = ((lane >> 3) & 1) << 4;

    for (int c = 0; c < 16; c++) {
        if (c < 15) {
            gemm_issue_loads(sbase + ((c + 1) & 1) * STAGE_B, c + 1, m0, n0, tid);
            cp_commit();
            cp_wait<1>();
        } else {
            cp_wait<0>();
        }
        __syncthreads();

        const uint32_t buf = sbase + (c & 1) * STAGE_B;
        const uint32_t Ahi_b = buf;
        const uint32_t Alo_b = buf + TILE_B;
        const uint32_t Whi_b = buf + 2 * TILE_B;
        const uint32_t Wlo_b = buf + 3 * TILE_B;

#pragma unroll
        for (int ks = 0; ks < 4; ks++) {
            const uint32_t kso = ks * 32;
            uint32_t ah[4][4], bh[4][2];
#pragma unroll
            for (int mt = 0; mt < 4; mt++)
                LDSM4(ah[mt], Ahi_b + (a_row + mt * 16) * TROW + kso + a_coh);
#pragma unroll
            for (int g = 0; g < 2; g++) {
                uint32_t t4[4];
                LDSM4(t4, Whi_b + (wn + g * 16 + b_rlo) * TROW + kso + b_coh);
                bh[g * 2][0] = t4[0]; bh[g * 2][1] = t4[1];
                bh[g * 2 + 1][0] = t4[2]; bh[g * 2 + 1][1] = t4[3];
            }
#pragma unroll
            for (int mt = 0; mt < 4; mt++)
#pragma unroll
                for (int nt = 0; nt < 4; nt++)
                    MMA16816(acc[mt][nt], ah[mt], bh[nt]);

            uint32_t bl[4][2];
#pragma unroll
            for (int g = 0; g < 2; g++) {
                uint32_t t4[4];
                LDSM4(t4, Wlo_b + (wn + g * 16 + b_rlo) * TROW + kso + b_coh);
                bl[g * 2][0] = t4[0]; bl[g * 2][1] = t4[1];
                bl[g * 2 + 1][0] = t4[2]; bl[g * 2 + 1][1] = t4[3];
            }
#pragma unroll
            for (int mt = 0; mt < 4; mt++)
#pragma unroll
                for (int nt = 0; nt < 4; nt++)
                    MMA16816(acc[mt][nt], ah[mt], bl[nt]);

            uint32_t al[4][4];
#pragma unroll
            for (int mt = 0; mt < 4; mt++)
                LDSM4(al[mt], Alo_b + (a_row + mt * 16) * TROW + kso + a_coh);
#pragma unroll
            for (int mt = 0; mt < 4; mt++)
#pragma unroll
                for (int nt = 0; nt < 4; nt++)
                    MMA16816(acc[mt][nt], al[mt], bh[nt]);
        }
        __syncthreads();
    }

    const int r_lo = lane >> 2;
    const int cpos = (lane & 3) * 2;
#pragma unroll
    for (int mt = 0; mt < 4; mt++) {
        int row0 = m0 + wm + mt * 16 + r_lo;
#pragma unroll
        for (int nt = 0; nt < 4; nt++) {
            int cl = wn + nt * 8 + cpos;
            float bx = sbias[cl], by = sbias[cl + 1];
            float2 v0 = make_float2(acc[mt][nt][0] + bx, acc[mt][nt][1] + by);
            float2 v1 = make_float2(acc[mt][nt][2] + bx, acc[mt][nt][3] + by);
            *(float2*)&g_xg[(size_t)row0 * GG + n0 + cl] = v0;
            *(float2*)&g_xg[(size_t)(row0 + 8) * GG + n0 + cl] = v1;
        }
    }
}

// ---------------- tensor-core persistent recurrence, warp-private staging ----------------
// 128 CTAs x 128 threads (4 warps). CTA owns 8 hidden units -> 32 gate rows.
// W_hh hi/lo resident in smem. h staged per-warp (each warp loads ONLY its 16
// batch rows): no CTA-wide sync in the k-loop, 4-deep cp.async pipeline over
// 16 chunks of 64 k. c in registers; grid barrier once per step.
#define WROW 2064                       // 1024 bf16 + 16B pad
#define WS_B (32 * WROW)                // 66048 per array
#define RROW 144                        // 64 bf16 + 16B pad
#define RBUF_B (16 * RROW)              // 2304: one warp-chunk, one array
#define RSTG_B (2 * RBUF_B)             // 4608: hi + lo
#define NBUF 4
#define WARP_STG (NBUF * RSTG_B)        // 18432 per warp
#define REC_SMEM (2 * WS_B + 4 * WARP_STG)   // 205824

__global__ void zero_rec() {
    int i = blockIdx.x * blockDim.x + threadIdx.x;
    if (i == 0) { g_gen = 0u; g_cnt = 0u; }
    uint32_t* p1 = (uint32_t*)g_ghi;
    uint32_t* p2 = (uint32_t*)g_glo;
    for (int k = i; k < 65536; k += gridDim.x * blockDim.x) { p1[k] = 0u; p2[k] = 0u; }
}

// issue one 64-k chunk for this warp's 16 batch rows (hi+lo), 8 cp.async16/lane
__device__ __forceinline__ void rec_stage_w(uint32_t dst, const __nv_bfloat16* ghi,
                                            const __nv_bfloat16* glo, int wid, int c, int lane) {
#pragma unroll
    for (int i = 0; i < 4; i++) {
        int idx = lane + i * 32;          // 0..127
        int r = idx >> 3, s = idx & 7;    // 16 rows x 8 sectors
        uint32_t d = dst + r * RROW + s * 16;
        size_t so = (size_t)(wid * 16 + r) * 1024 + c * 64 + s * 8;
        cp_async16(d, ghi + so);
        cp_async16(d + RBUF_B, glo + so);
    }
    cp_commit();
}

template<int LAYER>
__global__ void __launch_bounds__(128, 1)
lstm_rec_tc(float* __restrict__ out_ext)
{
    extern __shared__ char smraw[];
    const uint32_t sb = smem_u32(smraw);
    const uint32_t ws_hi = sb;
    const uint32_t ws_lo = sb + WS_B;

    const int tid = threadIdx.x;
    const int lane = tid & 31, wid = tid >> 5;
    const int j0 = blockIdx.x * 8;
    const uint32_t wstg = sb + 2 * WS_B + wid * WARP_STG;

    // Load W_hh hi/lo (32 rows) into smem once
#pragma unroll 4
    for (int n = 0; n < 32; n++) {
        int grow = ((n >> 3) << 10) + j0 + (n & 7);
        cp_async16(ws_hi + n * WROW + tid * 16, g_Whi + ((size_t)grow << 10) + tid * 8);
        cp_async16(ws_lo + n * WROW + tid * 16, g_Wlo + ((size_t)grow << 10) + tid * 8);
    }
    cp_commit(); cp_wait<0>();
    __syncthreads();

    const uint32_t a_off = (lane & 15) * RROW + ((lane >> 4) << 4);
    const uint32_t w_off = ((lane >> 4) * 8 + (lane & 7)) * WROW + (((lane >> 3) & 1) << 4);

    // cell mapping: acc[nt][0]=(r0,c0) [1]=(r0,c1) [2]=(r0+8,c0) [3]=(r0+8,c1); gate=nt
    const int r0 = lane >> 2;
    const int c0 = (lane & 3) * 2;
    const int bA = wid * 16 + r0;
    const int bB = bA + 8;
    const int jj = j0 + c0;

    float cst[4] = {0.f, 0.f, 0.f, 0.f};
    unsigned gen = 0;

    for (int t = 0; t < TT; t++) {
        const __nv_bfloat16* ghi_in = g_ghi[t & 1];
        const __nv_bfloat16* glo_in = g_glo[t & 1];
        __nv_bfloat16* ghi_out = g_ghi[(t + 1) & 1];
        __nv_bfloat16* glo_out = g_glo[(t + 1) & 1];

        // prefetch xg for this thread's cells (overlaps with staging)
        float2 xgv[2][4];
#pragma unroll
        for (int rp = 0; rp < 2; rp++) {
            size_t base = ((size_t)t * BB + (rp ? bB : bA)) * GG + jj;
#pragma unroll
            for (int g = 0; g < 4; g++)
                xgv[rp][g] = *(const float2*)&g_xg[base + (size_t)g * HH];
        }

        float acc[4][4];
#pragma unroll
        for (int nt = 0; nt < 4; nt++)
#pragma unroll
            for (int q = 0; q < 4; q++) acc[nt][q] = 0.f;

        // prologue: fill 3 pipeline stages
        rec_stage_w(wstg + 0 * RSTG_B, ghi_in, glo_in, wid, 0, lane);
        rec_stage_w(wstg + 1 * RSTG_B, ghi_in, glo_in, wid, 1, lane);
        rec_stage_w(wstg + 2 * RSTG_B, ghi_in, glo_in, wid, 2, lane);

        for (int c = 0; c < 16; c++) {
            if (c < 13) {
                rec_stage_w(wstg + ((c + 3) & 3) * RSTG_B, ghi_in, glo_in, wid, c + 3, lane);
                cp_wait<3>();
            } else if (c == 13) cp_wait<2>();
            else if (c == 14) cp_wait<1>();
            else cp_wait<0>();
            __syncwarp();

            const uint32_t abuf = wstg + (c & 3) * RSTG_B;
#pragma unroll
            for (int kl = 0; kl < 4; kl++) {
                const uint32_t Aad = abuf + a_off + kl * 32;
                const uint32_t kby = (uint32_t)(c * 64 + kl * 16) * 2;

                uint32_t ah[4], al[4], bh[4][2], bl[4][2];
                LDSM4(ah, Aad);
                LDSM4(al, Aad + RBUF_B);
                {
                    uint32_t t4[4];
                    LDSM4(t4, ws_hi + w_off + kby);
                    bh[0][0] = t4[0]; bh[0][1] = t4[1]; bh[1][0] = t4[2]; bh[1][1] = t4[3];
                    LDSM4(t4, ws_hi + 16 * WROW + w_off + kby);
                    bh[2][0] = t4[0]; bh[2][1] = t4[1]; bh[3][0] = t4[2]; bh[3][1] = t4[3];
                    LDSM4(t4, ws_lo + w_off + kby);
                    bl[0][0] = t4[0]; bl[0][1] = t4[1]; bl[1][0] = t4[2]; bl[1][1] = t4[3];
                    LDSM4(t4, ws_lo + 16 * WROW + w_off + kby);
                    bl[2][0] = t4[0]; bl[2][1] = t4[1]; bl[3][0] = t4[2]; bl[3][1] = t4[3];
                }
#pragma unroll
                for (int nt = 0; nt < 4; nt++) {
                    MMA16816(acc[nt], ah, bh[nt]);
                    MMA16816(acc[nt], al, bh[nt]);
                    MMA16816(acc[nt], ah, bl[nt]);
                }
            }
        }

        // pointwise LSTM update (thread-local cells)
#pragma unroll
        for (int rp = 0; rp < 2; rp++) {
            const int b = rp ? bB : bA;
            float hn[2];
#pragma unroll
            for (int cc = 0; cc < 2; cc++) {
                const int q = rp * 2 + cc;
                float pi = acc[0][q] + (cc ? xgv[rp][0].y : xgv[rp][0].x);
                float pf = acc[1][q] + (cc ? xgv[rp][1].y : xgv[rp][1].x);
                float pg = acc[2][q] + (cc ? xgv[rp][2].y : xgv[rp][2].x);
                float po = acc[3][q] + (cc ? xgv[rp][3].y : xgv[rp][3].x);
                float ig = 1.f / (1.f + expf(-pi));
                float fg = 1.f / (1.f + expf(-pf));
                float gc = tanhf(pg);
                float og = 1.f / (1.f + expf(-po));
                float cn = fg * cst[q] + ig * gc;
                cst[q] = cn;
                hn[cc] = og * tanhf(cn);
            }
            __nv_bfloat16 h0 = __float2bfloat16(hn[0]);
            __nv_bfloat16 h1 = __float2bfloat16(hn[1]);
            __nv_bfloat16 l0 = __float2bfloat16(hn[0] - __bfloat162float(h0));
            __nv_bfloat16 l1 = __float2bfloat16(hn[1] - __bfloat162float(h1));
            *(__nv_bfloat162*)&ghi_out[(size_t)b * HH + jj] = __nv_bfloat162(h0, h1);
            *(__nv_bfloat162*)&glo_out[(size_t)b * HH + jj] = __nv_bfloat162(l0, l1);
            float2 hv = make_float2(hn[0], hn[1]);
            if (LAYER == 0) *(float2*)&g_h1[((size_t)t * BB + b) * HH + jj] = hv;
            else            *(float2*)&out_ext[((size_t)b * TT + t) * HH + jj] = hv;
        }

        // grid barrier
        __threadfence();
        __syncthreads();
        gen++;
        if (tid == 0) {
            if (atomicAdd(&g_cnt, 1u) == NCTA - 1) {
                g_cnt = 0u;
                __threadfence();
                *(volatile unsigned*)&g_gen = gen;
            } else {
                while (*(volatile unsigned*)&g_gen < gen) { }
                __threadfence();
            }
        }
        __syncthreads();
    }
}

// ---------------- launch ----------------
extern "C" void kernel_launch(void* const* d_in, const int* in_sizes, int n_in,
                              void* d_out, int out_size)
{
    (void)in_sizes; (void)n_in; (void)out_size;
    const float* x     = (const float*)d_in[0];
    const float* W_ih0 = (const float*)d_in[1];
    const float* W_hh0 = (const float*)d_in[2];
    const float* b_ih0 = (const float*)d_in[3];
    const float* b_hh0 = (const float*)d_in[4];
    const float* W_ih1 = (const float*)d_in[5];
    const float* W_hh1 = (const float*)d_in[6];
    const float* b_ih1 = (const float*)d_in[7];
    const float* b_hh1 = (const float*)d_in[8];
    float* out = (float*)d_out;

    cudaFuncSetAttribute(gemm_bf16_split, cudaFuncAttributeMaxDynamicSharedMemorySize, GEMM_SMEM);
    cudaFuncSetAttribute(lstm_rec_tc<0>, cudaFuncAttributeMaxDynamicSharedMemorySize, REC_SMEM);
    cudaFuncSetAttribute(lstm_rec_tc<1>, cudaFuncAttributeMaxDynamicSharedMemorySize, REC_SMEM);

    const size_t convW_n = (size_t)GG * 1024;
    const size_t convA_n = (size_t)TT * BB * 1024;
    dim3 gemm_grid(GG / 128, (TT * BB) / 128);

    // ---- Layer 0 ----
    conv_split<<<(int)((convW_n + 255) / 256), 256>>>(W_ih0, DIN, 0);
    conv_split<<<(int)((convA_n + 255) / 256), 256>>>(x, DIN, 1);
    gemm_bf16_split<<<gemm_grid, 256, GEMM_SMEM>>>(b_ih0, b_hh0);
    conv_split<<<(int)((convW_n + 255) / 256), 256>>>(W_hh0, HH, 0);
    zero_rec<<<256, 256>>>();
    lstm_rec_tc<0><<<NCTA, 128, REC_SMEM>>>(out);

    // ---- Layer 1 ----
    conv_split<<<(int)((convW_n + 255) / 256), 256>>>(W_ih1, HH, 0);
    conv_split<<<(int)((convA_n + 255) / 256), 256>>>(nullptr, HH, 2);
    gemm_bf16_split<<<gemm_grid, 256, GEMM_SMEM>>>(b_ih1, b_hh1);
    conv_split<<<(int)((convW_n + 255) / 256), 256>>>(W_hh1, HH, 0);
    zero_rec<<<256, 256>>>();
    lstm_rec_tc<1><<<NCTA, 128, REC_SMEM>>>(out);
}